// round 14
// baseline (speedup 1.0000x reference)
#include <cuda_runtime.h>
#include <cstdint>

// LinearKoopmanLayer: per-(b,f) complex rotation of channel pair (2f, 2f+1).
// x: (B=256, 2F=128, T=1024) fp32, out same shape.
//   a = amp[f]^dt[b];  c = a*cos(freq[f]*dt[b]);  s = a*sin(freq[f]*dt[b])
//   out[b,2f,t]   = c*x0 - s*x1
//   out[b,2f+1,t] = s*x0 + c*x1
//
// R14 experiment: PERSISTENT single-wave grid. Prior best (4096 CTAs x 256,
// MLP8, default cache) = 35.9-36.5us, pinned at DRAM ~74%. That config runs
// 3.46 waves; the T_chip model charges (n_waves-1)*T_wave_trans (~1.3us ea)
// plus a ragged 0.46-wave tail. Here: grid = 148 SMs * 8 CTAs = 1184 (one
// wave), each CTA grid-strides over 3-4 block-tiles. Zero wave transitions;
// tail keeps ~500 CTAs resident (DRAM stays fed). Everything else identical
// to the pinned optimum (per-tile layout, MLP=8, default cache, fast
// intrinsics). If neutral, wave overhead was already hidden -> R4 final.

#define B_DIM 256
#define F_DIM 64
#define T_DIM 1024
#define T_VEC (T_DIM / 4)      // 256 float4 per row
#define BF_PER_BLOCK 4
#define NUM_TILES ((B_DIM * F_DIM) / BF_PER_BLOCK)   // 4096 block-tiles
#define GRID_PERSIST (148 * 8)                       // 1184 = one full wave

__global__ __launch_bounds__(256, 8)
void koopman_kernel(const float* __restrict__ x,
                    const float* __restrict__ delta_t,
                    const float* __restrict__ amplitudes,
                    const float* __restrict__ frequencies,
                    float* __restrict__ out) {
    const int lane6 = threadIdx.x >> 6;   // which pair within the block
    const int t0    = threadIdx.x & 63;

    for (int tile = blockIdx.x; tile < NUM_TILES; tile += GRID_PERSIST) {
        const int bf = tile * BF_PER_BLOCK + lane6;   // b*64+f
        const int b  = bf >> 6;
        const int f  = bf & 63;

        // Scalar loads first: longest dep chain (LDG -> pow -> sincos).
        // Tiny tables (256 + 64 + 64 floats) -> L1/L2 resident after iter 1.
        const float d   = __ldg(&delta_t[b]);
        const float amp = __ldg(&amplitudes[f]);
        const float frq = __ldg(&frequencies[f]);

        // rows 2f, 2f+1 of batch b -> global rows 2*bf, 2*bf+1
        const size_t base = (size_t)bf * (2 * T_DIM);
        const float4* __restrict__ x0 = reinterpret_cast<const float4*>(x + base);
        const float4* __restrict__ x1 = x0 + T_VEC;
        float4* __restrict__ o0 = reinterpret_cast<float4*>(out + base);
        float4* __restrict__ o1 = o0 + T_VEC;

        // Front-batch all 8 vector loads (MLP=8), default cache policy.
        float4 v0[4], v1[4];
#pragma unroll
        for (int i = 0; i < 4; i++) v0[i] = x0[t0 + 64 * i];
#pragma unroll
        for (int i = 0; i < 4; i++) v1[i] = x1[t0 + 64 * i];

        // Coefficient: fast intrinsics (rel_err 4e-7 << 1e-3 budget),
        // latency hidden under the outstanding loads.
        const float a = __powf(amp, d);     // amp in [0.7,1.3], d in [0.5,2]
        float s, c;
        __sincosf(frq * d, &s, &c);         // ang in [0, 4*pi]
        c *= a;
        s *= a;

#pragma unroll
        for (int i = 0; i < 4; i++) {
            float4 r0, r1;
            r0.x = c * v0[i].x - s * v1[i].x;  r1.x = s * v0[i].x + c * v1[i].x;
            r0.y = c * v0[i].y - s * v1[i].y;  r1.y = s * v0[i].y + c * v1[i].y;
            r0.z = c * v0[i].z - s * v1[i].z;  r1.z = s * v0[i].z + c * v1[i].z;
            r0.w = c * v0[i].w - s * v1[i].w;  r1.w = s * v0[i].w + c * v1[i].w;
            o0[t0 + 64 * i] = r0;
            o1[t0 + 64 * i] = r1;
        }
    }
}

extern "C" void kernel_launch(void* const* d_in, const int* in_sizes, int n_in,
                              void* d_out, int out_size) {
    const float* x           = (const float*)d_in[0];
    const float* delta_t     = (const float*)d_in[1];
    const float* amplitudes  = (const float*)d_in[2];
    const float* frequencies = (const float*)d_in[3];
    float* out = (float*)d_out;

    dim3 grid(GRID_PERSIST);   // 1184 CTAs = exactly one wave at occ 8
    dim3 block(256);
    koopman_kernel<<<grid, block>>>(x, delta_t, amplitudes, frequencies, out);
}

// round 15
// speedup vs baseline: 1.0668x; 1.0668x over previous
#include <cuda_runtime.h>
#include <cstdint>

// LinearKoopmanLayer: per-(b,f) complex rotation of channel pair (2f, 2f+1).
// x: (B=256, 2F=128, T=1024) fp32, out same shape.
//   a = amp[f]^dt[b];  c = a*cos(freq[f]*dt[b]);  s = a*sin(freq[f]*dt[b])
//   out[b,2f,t]   = c*x0 - s*x1
//   out[b,2f+1,t] = s*x0 + c*x1
//
// FINAL — exhaustive sweep, every axis measured (kernel us):
//   grid/block: 16384x256 36.7 | 4096x256* 35.9 | 2048x512 36.7
//               | 1184 persistent 38.5 (grid-stride loop serializes tiles:
//                 reg-block WAR across iterations kills cross-tile MLP)
//   MLP/thread: 2 -> 36.7 | 8* -> 35.9 | 16 -> 36.7 (ptxas re-batches)
//   cache:      default* 35.9 | stcs 37.5 | ldcs+stcs 46.9 (.cs costs
//               extra L1tex wavefronts on sm_103a)
//   width:      LDG.128* 35.9 | v8.f32 43.6 (within-instr wavefront replays)
//   (* = this kernel; reproduced 4x at 35.9-36.5)
// Pinned at the memory ceiling: 268.4 MB / 36us = 7.4 TB/s apparent L2
// throughput; DRAM 74-75% = read/write-turnaround ceiling for a 50/50 fp32
// stream. Traffic irreducible. Compute <6%, issue ~10.7%.
//
// Layout: 64 threads per (b,f) pair, each thread 4 float4 per row at
// t0+{0,64,128,192} (warp-coalesced 128B sectors), 8 front-batched loads;
// 4 pairs per 256-thread CTA, grid 4096. Coefficient (pow+sincos) once per
// thread via fast intrinsics, latency hidden under the outstanding loads.
// rel_err 4.0e-7 << 1e-3 budget.

#define B_DIM 256
#define F_DIM 64
#define T_DIM 1024
#define T_VEC (T_DIM / 4)      // 256 float4 per row
#define BF_PER_BLOCK 4

__global__ __launch_bounds__(256, 8)
void koopman_kernel(const float* __restrict__ x,
                    const float* __restrict__ delta_t,
                    const float* __restrict__ amplitudes,
                    const float* __restrict__ frequencies,
                    float* __restrict__ out) {
    const int bf = blockIdx.x * BF_PER_BLOCK + (threadIdx.x >> 6);  // b*64+f
    const int t0 = threadIdx.x & 63;
    const int b  = bf >> 6;
    const int f  = bf & 63;

    // Scalar loads first: they head the longest dep chain (LDG -> pow -> sincos).
    const float d   = __ldg(&delta_t[b]);
    const float amp = __ldg(&amplitudes[f]);
    const float frq = __ldg(&frequencies[f]);

    // rows 2f, 2f+1 of batch b -> global rows 2*bf, 2*bf+1 (contiguous 2 KB)
    const size_t base = (size_t)bf * (2 * T_DIM);
    const float4* __restrict__ x0 = reinterpret_cast<const float4*>(x + base);
    const float4* __restrict__ x1 = x0 + T_VEC;
    float4* __restrict__ o0 = reinterpret_cast<float4*>(out + base);
    float4* __restrict__ o1 = o0 + T_VEC;

    // Front-batch all 8 vector loads (MLP=8), default cache policy.
    float4 v0[4], v1[4];
#pragma unroll
    for (int i = 0; i < 4; i++) v0[i] = x0[t0 + 64 * i];
#pragma unroll
    for (int i = 0; i < 4; i++) v1[i] = x1[t0 + 64 * i];

    // Coefficient: once per thread, fast intrinsics (err << 1e-3 budget).
    const float a = __powf(amp, d);         // amp in [0.7,1.3], d in [0.5,2]
    float s, c;
    __sincosf(frq * d, &s, &c);             // ang in [0, 4*pi]
    c *= a;
    s *= a;

#pragma unroll
    for (int i = 0; i < 4; i++) {
        float4 r0, r1;
        r0.x = c * v0[i].x - s * v1[i].x;  r1.x = s * v0[i].x + c * v1[i].x;
        r0.y = c * v0[i].y - s * v1[i].y;  r1.y = s * v0[i].y + c * v1[i].y;
        r0.z = c * v0[i].z - s * v1[i].z;  r1.z = s * v0[i].z + c * v1[i].z;
        r0.w = c * v0[i].w - s * v1[i].w;  r1.w = s * v0[i].w + c * v1[i].w;
        o0[t0 + 64 * i] = r0;
        o1[t0 + 64 * i] = r1;
    }
}

extern "C" void kernel_launch(void* const* d_in, const int* in_sizes, int n_in,
                              void* d_out, int out_size) {
    const float* x           = (const float*)d_in[0];
    const float* delta_t     = (const float*)d_in[1];
    const float* amplitudes  = (const float*)d_in[2];
    const float* frequencies = (const float*)d_in[3];
    float* out = (float*)d_out;

    dim3 grid((B_DIM * F_DIM) / BF_PER_BLOCK);   // 4096 blocks
    dim3 block(256);
    koopman_kernel<<<grid, block>>>(x, delta_t, amplitudes, frequencies, out);
}